// round 6
// baseline (speedup 1.0000x reference)
#include <cuda_runtime.h>
#include <math.h>

#define DT 0.1f
#define EPS_STAT 0.01f
#define TCHUNKS 3

template <int BLOCK>
__global__ void __launch_bounds__(BLOCK)
kalman_kernel(const float* __restrict__ in, float* __restrict__ out,
              const float* __restrict__ sa_p, const float* __restrict__ so_p,
              const float* __restrict__ si_p,
              int B, int n_est, int n_pred) {
    __shared__ float4 gt[16];            // est: (K0, K1, s, 0)
    __shared__ float  st[64];            // pred: s
    __shared__ float  buf[2][BLOCK * 5]; // double-buffered [px,py,s,s,0] rows

    const int tid = threadIdx.x;
    const int blockStart = blockIdx.x * BLOCK;
    const bool fullBlock = (blockStart + BLOCK <= B);
    const int b = min(blockStart + tid, B - 1);
    const int total = n_est + n_pred;

    const int chunk = blockIdx.y;
    const int lo = (chunk * total) / TCHUNKS;        // first stored row
    const int hi = ((chunk + 1) * total) / TCHUNKS;  // one past last

    // ---- thread 0: uniform covariance recursion -> tables ----
    if (tid == 0) {
        const float sa = *sa_p, so = *so_p, si = *si_p;
        const float g0  = DT * DT * 0.5f;
        const float q00 = sa * sa * (g0 * g0);
        const float q01 = sa * sa * (g0 * DT);
        const float q11 = sa * sa * (DT * DT);
        const float r   = so * so;
        const float eps2 = EPS_STAT * EPS_STAT;
        float P00 = si * si, P01 = 0.0f, P11 = si * si;
        for (int k = 0; k < n_est; k++) {
            float a = P00 + 2.0f * DT * P01 + DT * DT * P11 + q00;
            float c = P01 + DT * P11 + q01;
            float d = P11 + q11;
            P00 = a; P01 = c; P11 = d;
            float S = P00 + r, rs = 1.0f / S;
            float K0 = P00 * rs, K1 = P01 * rs;
            float omk = 1.0f - K0;
            float A00 = omk * P00;
            float A01 = omk * P01;
            float A10 = P01 - K1 * P00;
            float A11 = P11 - K1 * P01;
            P00 =  A00 * omk      + r * K0 * K0;
            P01 = -A00 * K1 + A01 + r * K0 * K1;
            P11 = -A10 * K1 + A11 + r * K1 * K1;
            gt[k] = make_float4(K0, K1, sqrtf(fmaxf(P00, eps2)), 0.0f);
        }
        for (int j = 0; j < n_pred; j++) {
            float a = P00 + 2.0f * DT * P01 + DT * DT * P11 + q00;
            float c = P01 + DT * P11 + q01;
            float d = P11 + q11;
            P00 = a; P01 = c; P11 = d;
            st[j] = sqrtf(fmaxf(P00, eps2));
        }
    }

    // ---- init state ----
    const float2* __restrict__ zin = reinterpret_cast<const float2*>(in);
    float2 z0 = zin[b];
    float2 z1 = zin[(size_t)B + b];
    float px = z0.x, py = z0.y;
    float vx = (z1.x - z0.x) * (1.0f / DT);
    float vy = (z1.y - z0.y) * (1.0f / DT);
    float2 z = z1;

    buf[0][tid * 5 + 4] = 0.0f;   // constant zero slots, written once
    buf[1][tid * 5 + 4] = 0.0f;
    __syncthreads();

    // copy-out indexing: this chunk's stored rows [lo,hi) are contiguous
    constexpr int NF4 = BLOCK * 5 / 4;
    const long long rowF4o = (long long)B * 5 / 4;
    float4* __restrict__ drow = reinterpret_cast<float4*>(out)
        + (long long)lo * rowF4o + (long long)blockStart * 5 / 4;
    float* __restrict__ myrow0 = &buf[0][tid * 5];
    float* __restrict__ myrow1 = &buf[1][tid * 5];
    const bool extra = (tid < NF4 - BLOCK);
    int p = 0;  // buffer parity, advances only on stores

    // ---------- estimation recursion (all chunks run; chunk-owned rows stored) ----------
    for (int k = 0; k < n_est; k++) {
        px += DT * vx;
        py += DT * vy;
        float4 g = gt[k];
        float yx = z.x - px, yy = z.y - py;
        px += g.x * yx; vx += g.y * yx;
        py += g.x * yy; vy += g.y * yy;
        if (k + 1 < n_est) z = zin[(size_t)(k + 2) * B + b];

        if (k >= lo && k < hi) {
            float s = g.z;
            float* row = p ? myrow1 : myrow0;
            row[0] = px; row[1] = py; row[2] = s; row[3] = s;
            __syncthreads();
            if (fullBlock) {
                const float4* sbuf = reinterpret_cast<const float4*>(buf[p]);
                drow[tid] = sbuf[tid];
                if (extra) drow[tid + BLOCK] = sbuf[tid + BLOCK];
            } else if (blockStart + tid < B) {
                float* d = out + (long long)k * B * 5
                               + (long long)(blockStart + tid) * 5;
                d[0] = px; d[1] = py; d[2] = s; d[3] = s; d[4] = 0.0f;
            }
            drow += rowF4o;
            p ^= 1;
        }
    }

    // ---------- prediction rows (closed-form from est-final state) ----------
    const int t_lo = max(lo, n_est);
    for (int t = t_lo; t < hi; t++) {
        const int jp = t - n_est;
        const float tt = (float)(jp + 1) * DT;
        const float qx = fmaf(tt, vx, px);
        const float qy = fmaf(tt, vy, py);
        const float s  = st[jp];

        float* row = p ? myrow1 : myrow0;
        row[0] = qx; row[1] = qy; row[2] = s; row[3] = s;
        __syncthreads();
        if (fullBlock) {
            const float4* sbuf = reinterpret_cast<const float4*>(buf[p]);
            drow[tid] = sbuf[tid];
            if (extra) drow[tid + BLOCK] = sbuf[tid + BLOCK];
        } else if (blockStart + tid < B) {
            float* d = out + (long long)t * B * 5
                           + (long long)(blockStart + tid) * 5;
            d[0] = qx; d[1] = qy; d[2] = s; d[3] = s; d[4] = 0.0f;
        }
        drow += rowF4o;
        p ^= 1;
    }
}

extern "C" void kernel_launch(void* const* d_in, const int* in_sizes, int n_in,
                              void* d_out, int out_size) {
    const float* inputs  = (const float*)d_in[0];
    const float* sigma_a = (const float*)d_in[1];
    const float* sigma_o = (const float*)d_in[2];
    const float* sigma_i = (const float*)d_in[3];

    const int T_OBS = 10;
    const int B = in_sizes[0] / (T_OBS * 2);
    const int n_est = T_OBS - 1;                // 9
    const int totalSteps = out_size / (B * 5);  // 39
    const int n_pred = totalSteps - n_est;      // 30

    constexpr int BLOCK = 256;
    dim3 grid((B + BLOCK - 1) / BLOCK, TCHUNKS);
    kalman_kernel<BLOCK><<<grid, BLOCK>>>(inputs, (float*)d_out,
                                          sigma_a, sigma_o, sigma_i,
                                          B, n_est, n_pred);
}